// round 15
// baseline (speedup 1.0000x reference)
#include <cuda_runtime.h>
#include <cuda_bf16.h>
#include <math.h>
#include <stdint.h>

#define BB 2
#define TT 2048
#define CC 1024
#define HH 16
#define DD 64
#define NR 65                      // 2*MAXREL+1
#define BH (BB*HH)                 // 32
#define BT (BB*TT)                 // 4096
#define BLKM 256                   // q-rows per attention CTA (16 warps)

// ---------------- device scratch ----------------
__device__ float g_q[BH*TT*DD];        // fp32 q (for qrel)
__device__ float g_qrel[BH*TT*NR];     // [bh][t][r]
__device__ float g_y[BT*CC];           // fallback y sink
__device__ float g_att[(size_t)BH*TT*TT]; // fallback att sink

// bf16 hi/lo operands
__device__ __nv_bfloat16 g_qh[BH*TT*DD], g_ql[BH*TT*DD];   // [bh][t][d]
__device__ __nv_bfloat16 g_kh[BH*TT*DD], g_kl[BH*TT*DD];   // [bh][t][d]
__device__ __nv_bfloat16 g_vth[BH*DD*TT], g_vtl[BH*DD*TT]; // V^T [bh][d][t]
__device__ __nv_bfloat16 g_xa_hi[BT*CC],  g_xa_lo[BT*CC];
__device__ __nv_bfloat16 g_oa_hi[BT*CC],  g_oa_lo[BT*CC];  // written by attn
__device__ __nv_bfloat16 g_wta_hi[3*CC*CC], g_wta_lo[3*CC*CC];
__device__ __nv_bfloat16 g_wtp_hi[CC*CC],   g_wtp_lo[CC*CC];

// ===================== helpers =====================
__device__ __forceinline__ uint32_t smem_to_u32(const void* p) {
    uint32_t a;
    asm("{ .reg .u64 t; cvta.to.shared.u64 t, %1; cvt.u32.u64 %0, t; }" : "=r"(a) : "l"(p));
    return a;
}
__device__ __forceinline__ void cp_async16(uint32_t saddr, const void* gptr) {
    asm volatile("cp.async.cg.shared.global [%0], [%1], 16;" :: "r"(saddr), "l"(gptr));
}
#define CP_COMMIT() asm volatile("cp.async.commit_group;" ::: "memory")
#define CP_WAIT0()  asm volatile("cp.async.wait_group 0;" ::: "memory")
#define CP_WAIT1()  asm volatile("cp.async.wait_group 1;" ::: "memory")

__device__ __forceinline__ void mma_16816(float* c, const uint32_t* a, const uint32_t* b) {
    asm volatile("mma.sync.aligned.m16n8k16.row.col.f32.bf16.bf16.f32 "
        "{%0,%1,%2,%3}, {%4,%5,%6,%7}, {%8,%9}, {%0,%1,%2,%3};"
        : "+f"(c[0]), "+f"(c[1]), "+f"(c[2]), "+f"(c[3])
        : "r"(a[0]), "r"(a[1]), "r"(a[2]), "r"(a[3]), "r"(b[0]), "r"(b[1]));
}
__device__ __forceinline__ uint32_t pack_bf2(__nv_bfloat16 a, __nv_bfloat16 b) {
    return ((uint32_t)__bfloat16_as_ushort(b) << 16) | __bfloat16_as_ushort(a);
}
__device__ __forceinline__ uint32_t pack_hi_lo(float p0, float p1, uint32_t& lo) {
    __nv_bfloat16 h0 = __float2bfloat16(p0), h1 = __float2bfloat16(p1);
    __nv_bfloat16 l0 = __float2bfloat16(p0 - __bfloat162float(h0));
    __nv_bfloat16 l1 = __float2bfloat16(p1 - __bfloat162float(h1));
    lo = pack_bf2(l0, l1);
    return pack_bf2(h0, h1);
}

// =====================================================================
// Conversion kernels
// =====================================================================
__global__ __launch_bounds__(256) void split_kernel(const float* __restrict__ in)
{
    __nv_bfloat16* hi = g_xa_hi;
    __nv_bfloat16* lo = g_xa_lo;
    int i = blockIdx.x * 256 + threadIdx.x;
    float4 v = ((const float4*)in)[i];
    float a[4] = {v.x, v.y, v.z, v.w};
    __nv_bfloat16 hb[4], lb[4];
    #pragma unroll
    for (int c = 0; c < 4; c++) {
        hb[c] = __float2bfloat16(a[c]);
        lb[c] = __float2bfloat16(a[c] - __bfloat162float(hb[c]));
    }
    ((uint32_t*)hi)[i*2+0] = pack_bf2(hb[0], hb[1]);
    ((uint32_t*)hi)[i*2+1] = pack_bf2(hb[2], hb[3]);
    ((uint32_t*)lo)[i*2+0] = pack_bf2(lb[0], lb[1]);
    ((uint32_t*)lo)[i*2+1] = pack_bf2(lb[2], lb[3]);
}

template<int WSEL>  // 0: w_attn -> g_wta, 1: w_proj -> g_wtp
__global__ __launch_bounds__(256) void wsplit_kernel(const float* __restrict__ W, int N)
{
    __shared__ float ts[32][33];
    __nv_bfloat16* hi = (WSEL == 0) ? g_wta_hi : g_wtp_hi;
    __nv_bfloat16* lo = (WSEL == 0) ? g_wta_lo : g_wtp_lo;
    int nx = blockIdx.x * 32, kx = blockIdx.y * 32;
    int tx = threadIdx.x, ty = threadIdx.y;
    #pragma unroll
    for (int j = ty; j < 32; j += 8)
        ts[j][tx] = W[(size_t)(kx + j)*N + nx + tx];
    __syncthreads();
    #pragma unroll
    for (int j = ty; j < 32; j += 8) {
        float v = ts[tx][j];
        __nv_bfloat16 h = __float2bfloat16(v);
        __nv_bfloat16 l = __float2bfloat16(v - __bfloat162float(h));
        hi[(size_t)(nx + j)*CC + kx + tx] = h;
        lo[(size_t)(nx + j)*CC + kx + tx] = l;
    }
}

// =====================================================================
// mma.sync bf16x3 GEMM, cp.async double-buffered (unchanged from R9)
// =====================================================================
#define LDA 72
#define SM_ARR (128*LDA)
#define GEMM_BUF_BYTES (4*SM_ARR*2)
#define GEMM_SMEM_BYTES (2*GEMM_BUF_BYTES)

template<int MODE>
__global__ __launch_bounds__(256) void mma_gemm_kernel(const float* __restrict__ bias,
                                                       float* __restrict__ outp)
{
    extern __shared__ __nv_bfloat16 sb[];
    const uint32_t sbase = smem_to_u32(sb);

    const int tid  = threadIdx.x;
    const int wid  = tid >> 5, lane = tid & 31;
    const int wm   = wid >> 2, wn = wid & 3;
    const int m0   = blockIdx.y * 128;
    const int n0   = blockIdx.x * 128;

    const __nv_bfloat16* Ah = (MODE == 0) ? g_xa_hi : g_oa_hi;
    const __nv_bfloat16* Al = (MODE == 0) ? g_xa_lo : g_oa_lo;
    const __nv_bfloat16* Bh = (MODE == 0) ? g_wta_hi : g_wtp_hi;
    const __nv_bfloat16* Bl = (MODE == 0) ? g_wta_lo : g_wtp_lo;

    auto load_tile = [&](int kt, int buf) {
        const int k0 = kt * 64;
        const uint32_t b0 = sbase + (uint32_t)buf * GEMM_BUF_BYTES;
        #pragma unroll
        for (int it = 0; it < 4; it++) {
            int i = tid + it * 256;
            int r = i >> 3, c8 = i & 7;
            size_t ga = (size_t)(m0 + r) * CC + k0 + c8 * 8;
            size_t gb = (size_t)(n0 + r) * CC + k0 + c8 * 8;
            uint32_t so = (uint32_t)(r * LDA + c8 * 8) * 2;
            cp_async16(b0 + so,               &Ah[ga]);
            cp_async16(b0 + SM_ARR*2 + so,    &Al[ga]);
            cp_async16(b0 + 2*SM_ARR*2 + so,  &Bh[gb]);
            cp_async16(b0 + 3*SM_ARR*2 + so,  &Bl[gb]);
        }
        CP_COMMIT();
    };

    float acc[4][4][4];
    #pragma unroll
    for (int i = 0; i < 4; i++)
        #pragma unroll
        for (int j = 0; j < 4; j++)
            #pragma unroll
            for (int c = 0; c < 4; c++) acc[i][j][c] = 0.f;

    const int g  = lane >> 2;
    const int t2 = (lane & 3) * 2;

    load_tile(0, 0);

    for (int kt = 0; kt < 16; kt++) {
        CP_WAIT0();
        __syncthreads();
        if (kt + 1 < 16) load_tile(kt + 1, (kt + 1) & 1);

        const __nv_bfloat16* bAh = sb + (kt & 1) * (4*SM_ARR);
        const __nv_bfloat16* bAl = bAh + SM_ARR;
        const __nv_bfloat16* bBh = bAh + 2*SM_ARR;
        const __nv_bfloat16* bBl = bAh + 3*SM_ARR;

        #pragma unroll
        for (int ks = 0; ks < 4; ks++) {
            const int kb = ks * 16 + t2;
            uint32_t ah[4][4], al[4][4];
            #pragma unroll
            for (int tm = 0; tm < 4; tm++) {
                int r0 = (wm*64 + tm*16 + g) * LDA + kb;
                int r1 = r0 + 8 * LDA;
                ah[tm][0] = *(const uint32_t*)&bAh[r0];
                ah[tm][1] = *(const uint32_t*)&bAh[r1];
                ah[tm][2] = *(const uint32_t*)&bAh[r0 + 8];
                ah[tm][3] = *(const uint32_t*)&bAh[r1 + 8];
                al[tm][0] = *(const uint32_t*)&bAl[r0];
                al[tm][1] = *(const uint32_t*)&bAl[r1];
                al[tm][2] = *(const uint32_t*)&bAl[r0 + 8];
                al[tm][3] = *(const uint32_t*)&bAl[r1 + 8];
            }
            #pragma unroll
            for (int tn = 0; tn < 4; tn++) {
                int rb = (wn*32 + tn*8 + g) * LDA + kb;
                uint32_t bh[2], bl[2];
                bh[0] = *(const uint32_t*)&bBh[rb];
                bh[1] = *(const uint32_t*)&bBh[rb + 8];
                bl[0] = *(const uint32_t*)&bBl[rb];
                bl[1] = *(const uint32_t*)&bBl[rb + 8];
                #pragma unroll
                for (int tm = 0; tm < 4; tm++) {
                    mma_16816(acc[tm][tn], ah[tm], bh);
                    mma_16816(acc[tm][tn], ah[tm], bl);
                    mma_16816(acc[tm][tn], al[tm], bh);
                }
            }
        }
        __syncthreads();
    }

    const int lr = lane >> 2;
    const int lc = (lane & 3) * 2;
    #pragma unroll
    for (int tm = 0; tm < 4; tm++) {
        #pragma unroll
        for (int tn = 0; tn < 4; tn++) {
            int c = n0 + wn*32 + tn*8 + lc;
            float b0 = bias[c], b1 = bias[c+1];
            #pragma unroll
            for (int half = 0; half < 2; half++) {
                int m = m0 + wm*64 + tm*16 + lr + half*8;
                float v0 = acc[tm][tn][half*2+0] + b0;
                float v1 = acc[tm][tn][half*2+1] + b1;
                if (MODE == 0) {
                    int which = c >> 10, hh = (c >> 6) & 15, dd = c & 63;
                    int b_ = m >> 11, t_ = m & 2047;
                    int bhx = b_*HH + hh;
                    __nv_bfloat16 h0 = __float2bfloat16(v0);
                    __nv_bfloat16 h1 = __float2bfloat16(v1);
                    __nv_bfloat16 l0 = __float2bfloat16(v0 - __bfloat162float(h0));
                    __nv_bfloat16 l1 = __float2bfloat16(v1 - __bfloat162float(h1));
                    if (which == 0) {
                        size_t di = ((size_t)bhx*TT + t_)*DD + dd;
                        *(float2*)&g_q[di] = make_float2(v0, v1);
                        *(uint32_t*)&g_qh[di] = pack_bf2(h0, h1);
                        *(uint32_t*)&g_ql[di] = pack_bf2(l0, l1);
                    } else if (which == 1) {
                        size_t di = ((size_t)bhx*TT + t_)*DD + dd;
                        *(uint32_t*)&g_kh[di] = pack_bf2(h0, h1);
                        *(uint32_t*)&g_kl[di] = pack_bf2(l0, l1);
                    } else {
                        size_t vb = (size_t)bhx*DD;
                        g_vth[(vb + dd    )*TT + t_] = h0;
                        g_vth[(vb + dd + 1)*TT + t_] = h1;
                        g_vtl[(vb + dd    )*TT + t_] = l0;
                        g_vtl[(vb + dd + 1)*TT + t_] = l1;
                    }
                } else {
                    float* dst = outp ? outp : g_y;
                    *(float2*)&dst[(size_t)m*CC + c] = make_float2(v0, v1);
                }
            }
        }
    }
}

// =====================================================================
// qrel
// =====================================================================
__device__ __forceinline__ float dot4(float4 a, float4 b) {
    return a.x*b.x + a.y*b.y + a.z*b.z + a.w*b.w;
}

__global__ __launch_bounds__(256) void qrel_kernel(const float* __restrict__ rel)
{
    __shared__ float rs[NR*64];
    __shared__ float qs[32*64];
    const int tid = threadIdx.x;
    const int r0  = blockIdx.x * 32;

    for (int i = tid; i < NR*16; i += 256)
        ((float4*)rs)[i] = ((const float4*)rel)[i];
    for (int i = tid; i < 32*16; i += 256) {
        int t = i >> 4, d4 = i & 15;
        *(float4*)&qs[t*64 + d4*4] = *(const float4*)&g_q[(size_t)(r0+t)*64 + d4*4];
    }
    __syncthreads();

    for (int i = tid; i < 32*NR; i += 256) {
        int t = i / NR, r = i % NR;
        const float4* qq = (const float4*)&qs[t*64];
        const float4* rr = (const float4*)&rs[r*64];
        float acc = 0.f;
        #pragma unroll
        for (int d4 = 0; d4 < 16; d4++) acc += dot4(qq[d4], rr[d4]);
        g_qrel[(size_t)(r0+t)*NR + r] = acc;
    }
}

// =====================================================================
// Single-pass flash attention, 512 threads / 256 q-rows per CTA.
// cp.async double-buffered K/V staging; O written as bf16 hi/lo (g_oa).
// =====================================================================
#define SKW 72          // K smem row pitch (bf16)
#define SVW 136         // V^T smem row pitch (bf16)
#define NTH 512
#define KV_KH 0
#define KV_KL (128*SKW*2)
#define KV_VH (2*128*SKW*2)
#define KV_VL (2*128*SKW*2 + 64*SVW*2)
#define KV_BUF_BYTES (2*128*SKW*2 + 2*64*SVW*2)      // 71680
#define ATTN_SMEM_BYTES (2*KV_BUF_BYTES + BLKM*66*4 + BLKM*4 + 64)

__global__ __launch_bounds__(NTH, 1) void attn_kernel(float* __restrict__ out_att, int att_mode)
{
    extern __shared__ char smc[];
    const uint32_t sbase = smem_to_u32(smc);
    float* QR = (float*)(smc + 2*KV_BUF_BYTES);        // [256][66]
    float* sInv = QR + BLKM*66;                        // [256]

    const int tid = threadIdx.x, w = tid >> 5, lane = tid & 31;
    const int g = lane >> 2, t2 = (lane & 3) * 2;
    const int q0 = blockIdx.x * BLKM;
    const int bh = blockIdx.y;
    const int kend = q0 + BLKM;
    const size_t qbase = (size_t)bh * TT;
    float* att = att_mode ? g_att : out_att;

    // stage chunk (128 keys at kc) into buffer buf via cp.async
    auto stage = [&](int kc, int buf) {
        const uint32_t b0 = sbase + (uint32_t)buf * KV_BUF_BYTES;
        #pragma unroll
        for (int it = 0; it < 2; it++) {
            int i = tid + it * NTH;
            int r = i >> 3, c = i & 7;
            size_t gs = (qbase + kc + r)*DD + c*8;
            uint32_t so = (uint32_t)(r*SKW + c*8) * 2;
            cp_async16(b0 + KV_KH + so, &g_kh[gs]);
            cp_async16(b0 + KV_KL + so, &g_kl[gs]);
        }
        #pragma unroll
        for (int it = 0; it < 2; it++) {
            int i = tid + it * NTH;
            int d = i >> 4, c = i & 15;
            size_t gs = ((size_t)bh*DD + d)*TT + kc + c*8;
            uint32_t so = (uint32_t)(d*SVW + c*8) * 2;
            cp_async16(b0 + KV_VH + so, &g_vth[gs]);
            cp_async16(b0 + KV_VL + so, &g_vtl[gs]);
        }
        CP_COMMIT();
    };

    for (int i = tid; i < BLKM*NR; i += NTH) {
        int t = i / NR, r = i % NR;
        QR[t*66 + r] = g_qrel[(qbase + q0 + t)*NR + r];
    }

    const int tr0 = w*16 + g;
    const int r0 = q0 + tr0;
    const int r1 = r0 + 8;
    const int wmax = q0 + w*16 + 15;

    // Q fragments (hi/lo)
    uint32_t qfh[4][4], qfl[4][4];
    {
        size_t ra = (qbase + (size_t)r0) * DD;
        size_t rb = ra + 8*DD;
        #pragma unroll
        for (int ks = 0; ks < 4; ks++) {
            int c0 = ks*16 + t2;
            qfh[ks][0] = *(const uint32_t*)&g_qh[ra + c0];
            qfh[ks][1] = *(const uint32_t*)&g_qh[rb + c0];
            qfh[ks][2] = *(const uint32_t*)&g_qh[ra + c0 + 8];
            qfh[ks][3] = *(const uint32_t*)&g_qh[rb + c0 + 8];
            qfl[ks][0] = *(const uint32_t*)&g_ql[ra + c0];
            qfl[ks][1] = *(const uint32_t*)&g_ql[rb + c0];
            qfl[ks][2] = *(const uint32_t*)&g_ql[ra + c0 + 8];
            qfl[ks][3] = *(const uint32_t*)&g_ql[rb + c0 + 8];
        }
    }

    stage(0, 0);
    __syncthreads();
    const float qr0c = QR[tr0*66];        // rel constant for far tiles (idx 0)
    const float qr1c = QR[(tr0+8)*66];

    float o[8][4];
    #pragma unroll
    for (int dt = 0; dt < 8; dt++)
        #pragma unroll
        for (int c = 0; c < 4; c++) o[dt][c] = 0.f;
    float l0v = 0.f, l1v = 0.f;

    const size_t ab0 = (qbase + (size_t)r0) * TT;
    const size_t ab1 = (qbase + (size_t)r1) * TT;

    int cbuf = 0;
    for (int kc = 0; kc < kend; kc += 128, cbuf ^= 1) {
        if (kc + 128 < kend) stage(kc + 128, cbuf ^ 1);
        CP_COMMIT();                 // (possibly empty) keeps group count uniform
        CP_WAIT1();                  // chunk kc resident
        __syncthreads();

        const __nv_bfloat16* sKh = (const __nv_bfloat16*)(smc + cbuf*KV_BUF_BYTES + KV_KH);
        const __nv_bfloat16* sKl = (const __nv_bfloat16*)(smc + cbuf*KV_BUF_BYTES + KV_KL);
        const __nv_bfloat16* sVh = (const __nv_bfloat16*)(smc + cbuf*KV_BUF_BYTES + KV_VH);
        const __nv_bfloat16* sVl = (const __nv_bfloat16*)(smc + cbuf*KV_BUF_BYTES + KV_VL);

        #pragma unroll
        for (int ss2 = 0; ss2 < 4; ss2++) {       // 32-key sub-slices
            float p4[4][4];
            #pragma unroll
            for (int nt4 = 0; nt4 < 4; nt4++) {
                int nt = ss2*4 + nt4;
                int kbase = kc + nt*8;
                float c4[4] = {0.f, 0.f, 0.f, 0.f};
                if (kbase <= wmax) {
                    #pragma unroll
                    for (int ks = 0; ks < 4; ks++) {
                        int rb = (nt*8 + g)*SKW + ks*16 + t2;
                        uint32_t bh2[2], bl2[2];
                        bh2[0] = *(const uint32_t*)&sKh[rb];
                        bh2[1] = *(const uint32_t*)&sKh[rb + 8];
                        bl2[0] = *(const uint32_t*)&sKl[rb];
                        bl2[1] = *(const uint32_t*)&sKl[rb + 8];
                        mma_16816(c4, qfh[ks], bh2);
                        mma_16816(c4, qfh[ks], bl2);
                        mma_16816(c4, qfl[ks], bh2);
                    }
                }
                int kg = kbase + t2;
                if (kbase + 40 <= r0) {
                    // FAR tile: dist <= -33 for both rows -> rel idx 0, no mask
                    p4[nt4][0] = __expf((c4[0] + qr0c) * 0.125f);
                    p4[nt4][1] = __expf((c4[1] + qr0c) * 0.125f);
                    p4[nt4][2] = __expf((c4[2] + qr1c) * 0.125f);
                    p4[nt4][3] = __expf((c4[3] + qr1c) * 0.125f);
                    l0v += p4[nt4][0] + p4[nt4][1];
                    l1v += p4[nt4][2] + p4[nt4][3];
                } else {
                    {
                        int d0 = min(max(kg - r0, -32), 32) + 32;
                        int d1 = min(max(kg + 1 - r0, -32), 32) + 32;
                        float s0 = (c4[0] + QR[tr0*66 + d0]) * 0.125f;
                        float s1 = (c4[1] + QR[tr0*66 + d1]) * 0.125f;
                        p4[nt4][0] = (kg     <= r0) ? __expf(fminf(s0, 80.f)) : 0.f;
                        p4[nt4][1] = (kg + 1 <= r0) ? __expf(fminf(s1, 80.f)) : 0.f;
                        l0v += p4[nt4][0] + p4[nt4][1];
                    }
                    {
                        int d0 = min(max(kg - r1, -32), 32) + 32;
                        int d1 = min(max(kg + 1 - r1, -32), 32) + 32;
                        float s0 = (c4[2] + QR[(tr0+8)*66 + d0]) * 0.125f;
                        float s1 = (c4[3] + QR[(tr0+8)*66 + d1]) * 0.125f;
                        p4[nt4][2] = (kg     <= r1) ? __expf(fminf(s0, 80.f)) : 0.f;
                        p4[nt4][3] = (kg + 1 <= r1) ? __expf(fminf(s1, 80.f)) : 0.f;
                        l1v += p4[nt4][2] + p4[nt4][3];
                    }
                }
                *(float2*)&att[ab0 + kbase + t2] = make_float2(p4[nt4][0], p4[nt4][1]);
                *(float2*)&att[ab1 + kbase + t2] = make_float2(p4[nt4][2], p4[nt4][3]);
            }
            #pragma unroll
            for (int ksl = 0; ksl < 2; ksl++) {
                int kslice = kc + ss2*32 + ksl*16;
                if (kslice <= wmax) {
                    uint32_t ah[4], al[4];
                    ah[0] = pack_hi_lo(p4[2*ksl][0],   p4[2*ksl][1],   al[0]);
                    ah[1] = pack_hi_lo(p4[2*ksl][2],   p4[2*ksl][3],   al[1]);
                    ah[2] = pack_hi_lo(p4[2*ksl+1][0], p4[2*ksl+1][1], al[2]);
                    ah[3] = pack_hi_lo(p4[2*ksl+1][2], p4[2*ksl+1][3], al[3]);
                    int kloc = ss2*32 + ksl*16 + t2;
                    #pragma unroll
                    for (int dt = 0; dt < 8; dt++) {
                        int db = (dt*8 + g)*SVW + kloc;
                        uint32_t bh2[2], bl2[2];
                        bh2[0] = *(const uint32_t*)&sVh[db];
                        bh2[1] = *(const uint32_t*)&sVh[db + 8];
                        bl2[0] = *(const uint32_t*)&sVl[db];
                        bl2[1] = *(const uint32_t*)&sVl[db + 8];
                        mma_16816(o[dt], ah, bh2);
                        mma_16816(o[dt], ah, bl2);
                        mma_16816(o[dt], al, bh2);
                    }
                }
            }
        }
        __syncthreads();             // protect buffer before next-next stage
    }

    // ---- merge l across the quad (4 lanes share each row) ----
    #pragma unroll
    for (int off = 1; off <= 2; off <<= 1) {
        l0v += __shfl_xor_sync(0xffffffffu, l0v, off);
        l1v += __shfl_xor_sync(0xffffffffu, l1v, off);
    }
    const float inv0 = 1.f / l0v, inv1 = 1.f / l1v;
    if ((lane & 3) == 0) {
        sInv[tr0]     = inv0;
        sInv[tr0 + 8] = inv1;
    }

    // ---- write O scaled, directly as bf16 hi/lo (fused split for proj) ----
    {
        int b_ = bh >> 4, h_ = bh & 15;
        size_t ob0 = ((size_t)b_*TT + r0)*CC + h_*64;
        size_t ob1 = ((size_t)b_*TT + r1)*CC + h_*64;
        #pragma unroll
        for (int dt = 0; dt < 8; dt++) {
            uint32_t lo0, lo1;
            uint32_t hi0 = pack_hi_lo(o[dt][0]*inv0, o[dt][1]*inv0, lo0);
            uint32_t hi1 = pack_hi_lo(o[dt][2]*inv1, o[dt][3]*inv1, lo1);
            *(uint32_t*)&g_oa_hi[ob0 + dt*8 + t2] = hi0;
            *(uint32_t*)&g_oa_lo[ob0 + dt*8 + t2] = lo0;
            *(uint32_t*)&g_oa_hi[ob1 + dt*8 + t2] = hi1;
            *(uint32_t*)&g_oa_lo[ob1 + dt*8 + t2] = lo1;
        }
    }

    // ---- zero-fill att cols [kend, TT) ----
    {
        int zc4 = (TT - kend) >> 2;
        float4 z = make_float4(0.f, 0.f, 0.f, 0.f);
        if (zc4 > 0) {
            for (int i = tid; i < BLKM*zc4; i += NTH) {
                int row = i / zc4;
                int c4i = i - row*zc4;
                *(float4*)&att[(qbase + q0 + row)*TT + kend + c4i*4] = z;
            }
        }
    }

    // ---- in-CTA normalization sweep (rows just written, L2-hot) ----
    __syncthreads();
    for (int row = w; row < BLKM; row += 16) {
        float inv = sInv[row];
        int n = q0 + row + 1;
        int n4 = (n + 3) >> 2;
        float4* p = (float4*)(att + (qbase + q0 + row) * TT);
        for (int i = lane; i < n4; i += 32) {
            float4 v = p[i];
            v.x *= inv; v.y *= inv; v.z *= inv; v.w *= inv;
            p[i] = v;
        }
    }
}

// =====================================================================
extern "C" void kernel_launch(void* const* d_in, const int* in_sizes, int n_in,
                              void* d_out, int out_size)
{
    const float* x      = (const float*)d_in[0];
    const float* w_attn = (const float*)d_in[2];
    const float* b_attn = (const float*)d_in[3];
    const float* w_proj = (const float*)d_in[4];
    const float* b_proj = (const float*)d_in[5];
    const float* rel_k  = (const float*)d_in[6];
    float* out = (float*)d_out;

    const size_t YS = (size_t)BT*CC;
    const size_t AS = (size_t)BH*TT*TT;

    float* y_out = out;
    float* att_base = nullptr;
    int att_mode = 1;
    if ((size_t)out_size >= YS + AS) {
        y_out = out; att_base = out + YS; att_mode = 0;
    } else if ((size_t)out_size == AS) {
        att_base = out; att_mode = 0; y_out = nullptr;
    }

    cudaFuncSetAttribute(attn_kernel,
        cudaFuncAttributeMaxDynamicSharedMemorySize, ATTN_SMEM_BYTES);
    cudaFuncSetAttribute(mma_gemm_kernel<0>,
        cudaFuncAttributeMaxDynamicSharedMemorySize, GEMM_SMEM_BYTES);
    cudaFuncSetAttribute(mma_gemm_kernel<1>,
        cudaFuncAttributeMaxDynamicSharedMemorySize, GEMM_SMEM_BYTES);

    split_kernel<<<BT*CC/4/256, 256>>>(x);
    wsplit_kernel<0><<<dim3(3*CC/32, CC/32), dim3(32,8)>>>(w_attn, 3*CC);
    wsplit_kernel<1><<<dim3(CC/32,   CC/32), dim3(32,8)>>>(w_proj, CC);
    mma_gemm_kernel<0><<<dim3(24, 32), 256, GEMM_SMEM_BYTES>>>(b_attn, nullptr);
    qrel_kernel<<<BH*TT/32, 256>>>(rel_k);
    attn_kernel<<<dim3(TT/BLKM, BH), NTH, ATTN_SMEM_BYTES>>>(att_base, att_mode);
    mma_gemm_kernel<1><<<dim3(8, 32), 256, GEMM_SMEM_BYTES>>>(b_proj, y_out);
}

// round 16
// speedup vs baseline: 1.0029x; 1.0029x over previous
#include <cuda_runtime.h>
#include <cuda_bf16.h>
#include <math.h>
#include <stdint.h>

#define BB 2
#define TT 2048
#define CC 1024
#define HH 16
#define DD 64
#define NR 65                      // 2*MAXREL+1
#define BH (BB*HH)                 // 32
#define BT (BB*TT)                 // 4096
#define BLKM 256                   // q-rows per attention CTA (16 warps)

// ---------------- device scratch ----------------
__device__ float g_q[BH*TT*DD];        // fp32 q (for qrel)
__device__ float g_qrel[BH*TT*NR];     // [bh][t][r]
__device__ float g_y[BT*CC];           // fallback y sink
__device__ float g_att[(size_t)BH*TT*TT]; // fallback att sink

// bf16 hi/lo operands
__device__ __nv_bfloat16 g_qh[BH*TT*DD], g_ql[BH*TT*DD];   // [bh][t][d]
__device__ __nv_bfloat16 g_kh[BH*TT*DD], g_kl[BH*TT*DD];   // [bh][t][d]
__device__ __nv_bfloat16 g_vth[BH*DD*TT], g_vtl[BH*DD*TT]; // V^T [bh][d][t]
__device__ __nv_bfloat16 g_xa_hi[BT*CC],  g_xa_lo[BT*CC];
__device__ __nv_bfloat16 g_oa_hi[BT*CC],  g_oa_lo[BT*CC];  // written by attn
__device__ __nv_bfloat16 g_wta_hi[3*CC*CC], g_wta_lo[3*CC*CC];
__device__ __nv_bfloat16 g_wtp_hi[CC*CC],   g_wtp_lo[CC*CC];

// ===================== helpers =====================
__device__ __forceinline__ uint32_t smem_to_u32(const void* p) {
    uint32_t a;
    asm("{ .reg .u64 t; cvta.to.shared.u64 t, %1; cvt.u32.u64 %0, t; }" : "=r"(a) : "l"(p));
    return a;
}
__device__ __forceinline__ void cp_async16(uint32_t saddr, const void* gptr) {
    asm volatile("cp.async.cg.shared.global [%0], [%1], 16;" :: "r"(saddr), "l"(gptr));
}
#define CP_COMMIT() asm volatile("cp.async.commit_group;" ::: "memory")
#define CP_WAIT0()  asm volatile("cp.async.wait_group 0;" ::: "memory")
#define CP_WAIT1()  asm volatile("cp.async.wait_group 1;" ::: "memory")

__device__ __forceinline__ void mma_16816(float* c, const uint32_t* a, const uint32_t* b) {
    asm volatile("mma.sync.aligned.m16n8k16.row.col.f32.bf16.bf16.f32 "
        "{%0,%1,%2,%3}, {%4,%5,%6,%7}, {%8,%9}, {%0,%1,%2,%3};"
        : "+f"(c[0]), "+f"(c[1]), "+f"(c[2]), "+f"(c[3])
        : "r"(a[0]), "r"(a[1]), "r"(a[2]), "r"(a[3]), "r"(b[0]), "r"(b[1]));
}
__device__ __forceinline__ uint32_t pack_bf2(__nv_bfloat16 a, __nv_bfloat16 b) {
    return ((uint32_t)__bfloat16_as_ushort(b) << 16) | __bfloat16_as_ushort(a);
}
__device__ __forceinline__ uint32_t pack_hi_lo(float p0, float p1, uint32_t& lo) {
    __nv_bfloat16 h0 = __float2bfloat16(p0), h1 = __float2bfloat16(p1);
    __nv_bfloat16 l0 = __float2bfloat16(p0 - __bfloat162float(h0));
    __nv_bfloat16 l1 = __float2bfloat16(p1 - __bfloat162float(h1));
    lo = pack_bf2(l0, l1);
    return pack_bf2(h0, h1);
}

// =====================================================================
// Conversion kernels
// =====================================================================
__global__ __launch_bounds__(256) void split_kernel(const float* __restrict__ in)
{
    __nv_bfloat16* hi = g_xa_hi;
    __nv_bfloat16* lo = g_xa_lo;
    int i = blockIdx.x * 256 + threadIdx.x;
    float4 v = ((const float4*)in)[i];
    float a[4] = {v.x, v.y, v.z, v.w};
    __nv_bfloat16 hb[4], lb[4];
    #pragma unroll
    for (int c = 0; c < 4; c++) {
        hb[c] = __float2bfloat16(a[c]);
        lb[c] = __float2bfloat16(a[c] - __bfloat162float(hb[c]));
    }
    ((uint32_t*)hi)[i*2+0] = pack_bf2(hb[0], hb[1]);
    ((uint32_t*)hi)[i*2+1] = pack_bf2(hb[2], hb[3]);
    ((uint32_t*)lo)[i*2+0] = pack_bf2(lb[0], lb[1]);
    ((uint32_t*)lo)[i*2+1] = pack_bf2(lb[2], lb[3]);
}

template<int WSEL>  // 0: w_attn -> g_wta, 1: w_proj -> g_wtp
__global__ __launch_bounds__(256) void wsplit_kernel(const float* __restrict__ W, int N)
{
    __shared__ float ts[32][33];
    __nv_bfloat16* hi = (WSEL == 0) ? g_wta_hi : g_wtp_hi;
    __nv_bfloat16* lo = (WSEL == 0) ? g_wta_lo : g_wtp_lo;
    int nx = blockIdx.x * 32, kx = blockIdx.y * 32;
    int tx = threadIdx.x, ty = threadIdx.y;
    #pragma unroll
    for (int j = ty; j < 32; j += 8)
        ts[j][tx] = W[(size_t)(kx + j)*N + nx + tx];
    __syncthreads();
    #pragma unroll
    for (int j = ty; j < 32; j += 8) {
        float v = ts[tx][j];
        __nv_bfloat16 h = __float2bfloat16(v);
        __nv_bfloat16 l = __float2bfloat16(v - __bfloat162float(h));
        hi[(size_t)(nx + j)*CC + kx + tx] = h;
        lo[(size_t)(nx + j)*CC + kx + tx] = l;
    }
}

// =====================================================================
// mma.sync bf16x3 GEMM, cp.async double-buffered (unchanged from R9)
// =====================================================================
#define LDA 72
#define SM_ARR (128*LDA)
#define GEMM_BUF_BYTES (4*SM_ARR*2)
#define GEMM_SMEM_BYTES (2*GEMM_BUF_BYTES)

template<int MODE>
__global__ __launch_bounds__(256) void mma_gemm_kernel(const float* __restrict__ bias,
                                                       float* __restrict__ outp)
{
    extern __shared__ __nv_bfloat16 sb[];
    const uint32_t sbase = smem_to_u32(sb);

    const int tid  = threadIdx.x;
    const int wid  = tid >> 5, lane = tid & 31;
    const int wm   = wid >> 2, wn = wid & 3;
    const int m0   = blockIdx.y * 128;
    const int n0   = blockIdx.x * 128;

    const __nv_bfloat16* Ah = (MODE == 0) ? g_xa_hi : g_oa_hi;
    const __nv_bfloat16* Al = (MODE == 0) ? g_xa_lo : g_oa_lo;
    const __nv_bfloat16* Bh = (MODE == 0) ? g_wta_hi : g_wtp_hi;
    const __nv_bfloat16* Bl = (MODE == 0) ? g_wta_lo : g_wtp_lo;

    auto load_tile = [&](int kt, int buf) {
        const int k0 = kt * 64;
        const uint32_t b0 = sbase + (uint32_t)buf * GEMM_BUF_BYTES;
        #pragma unroll
        for (int it = 0; it < 4; it++) {
            int i = tid + it * 256;
            int r = i >> 3, c8 = i & 7;
            size_t ga = (size_t)(m0 + r) * CC + k0 + c8 * 8;
            size_t gb = (size_t)(n0 + r) * CC + k0 + c8 * 8;
            uint32_t so = (uint32_t)(r * LDA + c8 * 8) * 2;
            cp_async16(b0 + so,               &Ah[ga]);
            cp_async16(b0 + SM_ARR*2 + so,    &Al[ga]);
            cp_async16(b0 + 2*SM_ARR*2 + so,  &Bh[gb]);
            cp_async16(b0 + 3*SM_ARR*2 + so,  &Bl[gb]);
        }
        CP_COMMIT();
    };

    float acc[4][4][4];
    #pragma unroll
    for (int i = 0; i < 4; i++)
        #pragma unroll
        for (int j = 0; j < 4; j++)
            #pragma unroll
            for (int c = 0; c < 4; c++) acc[i][j][c] = 0.f;

    const int g  = lane >> 2;
    const int t2 = (lane & 3) * 2;

    load_tile(0, 0);

    for (int kt = 0; kt < 16; kt++) {
        CP_WAIT0();
        __syncthreads();
        if (kt + 1 < 16) load_tile(kt + 1, (kt + 1) & 1);

        const __nv_bfloat16* bAh = sb + (kt & 1) * (4*SM_ARR);
        const __nv_bfloat16* bAl = bAh + SM_ARR;
        const __nv_bfloat16* bBh = bAh + 2*SM_ARR;
        const __nv_bfloat16* bBl = bAh + 3*SM_ARR;

        #pragma unroll
        for (int ks = 0; ks < 4; ks++) {
            const int kb = ks * 16 + t2;
            uint32_t ah[4][4], al[4][4];
            #pragma unroll
            for (int tm = 0; tm < 4; tm++) {
                int r0 = (wm*64 + tm*16 + g) * LDA + kb;
                int r1 = r0 + 8 * LDA;
                ah[tm][0] = *(const uint32_t*)&bAh[r0];
                ah[tm][1] = *(const uint32_t*)&bAh[r1];
                ah[tm][2] = *(const uint32_t*)&bAh[r0 + 8];
                ah[tm][3] = *(const uint32_t*)&bAh[r1 + 8];
                al[tm][0] = *(const uint32_t*)&bAl[r0];
                al[tm][1] = *(const uint32_t*)&bAl[r1];
                al[tm][2] = *(const uint32_t*)&bAl[r0 + 8];
                al[tm][3] = *(const uint32_t*)&bAl[r1 + 8];
            }
            #pragma unroll
            for (int tn = 0; tn < 4; tn++) {
                int rb = (wn*32 + tn*8 + g) * LDA + kb;
                uint32_t bh[2], bl[2];
                bh[0] = *(const uint32_t*)&bBh[rb];
                bh[1] = *(const uint32_t*)&bBh[rb + 8];
                bl[0] = *(const uint32_t*)&bBl[rb];
                bl[1] = *(const uint32_t*)&bBl[rb + 8];
                #pragma unroll
                for (int tm = 0; tm < 4; tm++) {
                    mma_16816(acc[tm][tn], ah[tm], bh);
                    mma_16816(acc[tm][tn], ah[tm], bl);
                    mma_16816(acc[tm][tn], al[tm], bh);
                }
            }
        }
        __syncthreads();
    }

    const int lr = lane >> 2;
    const int lc = (lane & 3) * 2;
    #pragma unroll
    for (int tm = 0; tm < 4; tm++) {
        #pragma unroll
        for (int tn = 0; tn < 4; tn++) {
            int c = n0 + wn*32 + tn*8 + lc;
            float b0 = bias[c], b1 = bias[c+1];
            #pragma unroll
            for (int half = 0; half < 2; half++) {
                int m = m0 + wm*64 + tm*16 + lr + half*8;
                float v0 = acc[tm][tn][half*2+0] + b0;
                float v1 = acc[tm][tn][half*2+1] + b1;
                if (MODE == 0) {
                    int which = c >> 10, hh = (c >> 6) & 15, dd = c & 63;
                    int b_ = m >> 11, t_ = m & 2047;
                    int bhx = b_*HH + hh;
                    __nv_bfloat16 h0 = __float2bfloat16(v0);
                    __nv_bfloat16 h1 = __float2bfloat16(v1);
                    __nv_bfloat16 l0 = __float2bfloat16(v0 - __bfloat162float(h0));
                    __nv_bfloat16 l1 = __float2bfloat16(v1 - __bfloat162float(h1));
                    if (which == 0) {
                        size_t di = ((size_t)bhx*TT + t_)*DD + dd;
                        *(float2*)&g_q[di] = make_float2(v0, v1);
                        *(uint32_t*)&g_qh[di] = pack_bf2(h0, h1);
                        *(uint32_t*)&g_ql[di] = pack_bf2(l0, l1);
                    } else if (which == 1) {
                        size_t di = ((size_t)bhx*TT + t_)*DD + dd;
                        *(uint32_t*)&g_kh[di] = pack_bf2(h0, h1);
                        *(uint32_t*)&g_kl[di] = pack_bf2(l0, l1);
                    } else {
                        size_t vb = (size_t)bhx*DD;
                        g_vth[(vb + dd    )*TT + t_] = h0;
                        g_vth[(vb + dd + 1)*TT + t_] = h1;
                        g_vtl[(vb + dd    )*TT + t_] = l0;
                        g_vtl[(vb + dd + 1)*TT + t_] = l1;
                    }
                } else {
                    float* dst = outp ? outp : g_y;
                    *(float2*)&dst[(size_t)m*CC + c] = make_float2(v0, v1);
                }
            }
        }
    }
}

// =====================================================================
// qrel
// =====================================================================
__device__ __forceinline__ float dot4(float4 a, float4 b) {
    return a.x*b.x + a.y*b.y + a.z*b.z + a.w*b.w;
}

__global__ __launch_bounds__(256) void qrel_kernel(const float* __restrict__ rel)
{
    __shared__ float rs[NR*64];
    __shared__ float qs[32*64];
    const int tid = threadIdx.x;
    const int r0  = blockIdx.x * 32;

    for (int i = tid; i < NR*16; i += 256)
        ((float4*)rs)[i] = ((const float4*)rel)[i];
    for (int i = tid; i < 32*16; i += 256) {
        int t = i >> 4, d4 = i & 15;
        *(float4*)&qs[t*64 + d4*4] = *(const float4*)&g_q[(size_t)(r0+t)*64 + d4*4];
    }
    __syncthreads();

    for (int i = tid; i < 32*NR; i += 256) {
        int t = i / NR, r = i % NR;
        const float4* qq = (const float4*)&qs[t*64];
        const float4* rr = (const float4*)&rs[r*64];
        float acc = 0.f;
        #pragma unroll
        for (int d4 = 0; d4 < 16; d4++) acc += dot4(qq[d4], rr[d4]);
        g_qrel[(size_t)(r0+t)*NR + r] = acc;
    }
}

// =====================================================================
// Single-pass flash attention, 512 threads / 256 q-rows per CTA.
// cp.async double-buffered K/V staging; O written as bf16 hi/lo (g_oa).
// =====================================================================
#define SKW 72          // K smem row pitch (bf16)
#define SVW 136         // V^T smem row pitch (bf16)
#define NTH 512
#define KV_KH 0
#define KV_KL (128*SKW*2)
#define KV_VH (2*128*SKW*2)
#define KV_VL (2*128*SKW*2 + 64*SVW*2)
#define KV_BUF_BYTES (2*128*SKW*2 + 2*64*SVW*2)      // 71680
#define ATTN_SMEM_BYTES (2*KV_BUF_BYTES + BLKM*66*4 + BLKM*4 + 64)

__global__ __launch_bounds__(NTH, 1) void attn_kernel(float* __restrict__ out_att, int att_mode)
{
    extern __shared__ char smc[];
    const uint32_t sbase = smem_to_u32(smc);
    float* QR = (float*)(smc + 2*KV_BUF_BYTES);        // [256][66]
    float* sInv = QR + BLKM*66;                        // [256]

    const int tid = threadIdx.x, w = tid >> 5, lane = tid & 31;
    const int g = lane >> 2, t2 = (lane & 3) * 2;
    const int q0 = blockIdx.x * BLKM;
    const int bh = blockIdx.y;
    const int kend = q0 + BLKM;
    const size_t qbase = (size_t)bh * TT;
    float* att = att_mode ? g_att : out_att;

    // stage chunk (128 keys at kc) into buffer buf via cp.async
    auto stage = [&](int kc, int buf) {
        const uint32_t b0 = sbase + (uint32_t)buf * KV_BUF_BYTES;
        #pragma unroll
        for (int it = 0; it < 2; it++) {
            int i = tid + it * NTH;
            int r = i >> 3, c = i & 7;
            size_t gs = (qbase + kc + r)*DD + c*8;
            uint32_t so = (uint32_t)(r*SKW + c*8) * 2;
            cp_async16(b0 + KV_KH + so, &g_kh[gs]);
            cp_async16(b0 + KV_KL + so, &g_kl[gs]);
        }
        #pragma unroll
        for (int it = 0; it < 2; it++) {
            int i = tid + it * NTH;
            int d = i >> 4, c = i & 15;
            size_t gs = ((size_t)bh*DD + d)*TT + kc + c*8;
            uint32_t so = (uint32_t)(d*SVW + c*8) * 2;
            cp_async16(b0 + KV_VH + so, &g_vth[gs]);
            cp_async16(b0 + KV_VL + so, &g_vtl[gs]);
        }
        CP_COMMIT();
    };

    for (int i = tid; i < BLKM*NR; i += NTH) {
        int t = i / NR, r = i % NR;
        QR[t*66 + r] = g_qrel[(qbase + q0 + t)*NR + r];
    }

    const int tr0 = w*16 + g;
    const int r0 = q0 + tr0;
    const int r1 = r0 + 8;
    const int wmax = q0 + w*16 + 15;

    // Q fragments (hi/lo)
    uint32_t qfh[4][4], qfl[4][4];
    {
        size_t ra = (qbase + (size_t)r0) * DD;
        size_t rb = ra + 8*DD;
        #pragma unroll
        for (int ks = 0; ks < 4; ks++) {
            int c0 = ks*16 + t2;
            qfh[ks][0] = *(const uint32_t*)&g_qh[ra + c0];
            qfh[ks][1] = *(const uint32_t*)&g_qh[rb + c0];
            qfh[ks][2] = *(const uint32_t*)&g_qh[ra + c0 + 8];
            qfh[ks][3] = *(const uint32_t*)&g_qh[rb + c0 + 8];
            qfl[ks][0] = *(const uint32_t*)&g_ql[ra + c0];
            qfl[ks][1] = *(const uint32_t*)&g_ql[rb + c0];
            qfl[ks][2] = *(const uint32_t*)&g_ql[ra + c0 + 8];
            qfl[ks][3] = *(const uint32_t*)&g_ql[rb + c0 + 8];
        }
    }

    stage(0, 0);
    __syncthreads();
    const float qr0c = QR[tr0*66];        // rel constant for far tiles (idx 0)
    const float qr1c = QR[(tr0+8)*66];

    float o[8][4];
    #pragma unroll
    for (int dt = 0; dt < 8; dt++)
        #pragma unroll
        for (int c = 0; c < 4; c++) o[dt][c] = 0.f;
    float l0v = 0.f, l1v = 0.f;

    const size_t ab0 = (qbase + (size_t)r0) * TT;
    const size_t ab1 = (qbase + (size_t)r1) * TT;

    int cbuf = 0;
    for (int kc = 0; kc < kend; kc += 128, cbuf ^= 1) {
        if (kc + 128 < kend) stage(kc + 128, cbuf ^ 1);
        CP_COMMIT();                 // (possibly empty) keeps group count uniform
        CP_WAIT1();                  // chunk kc resident
        __syncthreads();

        const __nv_bfloat16* sKh = (const __nv_bfloat16*)(smc + cbuf*KV_BUF_BYTES + KV_KH);
        const __nv_bfloat16* sKl = (const __nv_bfloat16*)(smc + cbuf*KV_BUF_BYTES + KV_KL);
        const __nv_bfloat16* sVh = (const __nv_bfloat16*)(smc + cbuf*KV_BUF_BYTES + KV_VH);
        const __nv_bfloat16* sVl = (const __nv_bfloat16*)(smc + cbuf*KV_BUF_BYTES + KV_VL);

        #pragma unroll
        for (int ss2 = 0; ss2 < 4; ss2++) {       // 32-key sub-slices
            float p4[4][4];
            #pragma unroll
            for (int nt4 = 0; nt4 < 4; nt4++) {
                int nt = ss2*4 + nt4;
                int kbase = kc + nt*8;
                float c4[4] = {0.f, 0.f, 0.f, 0.f};
                if (kbase <= wmax) {
                    #pragma unroll
                    for (int ks = 0; ks < 4; ks++) {
                        int rb = (nt*8 + g)*SKW + ks*16 + t2;
                        uint32_t bh2[2], bl2[2];
                        bh2[0] = *(const uint32_t*)&sKh[rb];
                        bh2[1] = *(const uint32_t*)&sKh[rb + 8];
                        bl2[0] = *(const uint32_t*)&sKl[rb];
                        bl2[1] = *(const uint32_t*)&sKl[rb + 8];
                        mma_16816(c4, qfh[ks], bh2);
                        mma_16816(c4, qfh[ks], bl2);
                        mma_16816(c4, qfl[ks], bh2);
                    }
                }
                int kg = kbase + t2;
                if (kbase + 40 <= r0) {
                    // FAR tile: dist <= -33 for both rows -> rel idx 0, no mask
                    p4[nt4][0] = __expf((c4[0] + qr0c) * 0.125f);
                    p4[nt4][1] = __expf((c4[1] + qr0c) * 0.125f);
                    p4[nt4][2] = __expf((c4[2] + qr1c) * 0.125f);
                    p4[nt4][3] = __expf((c4[3] + qr1c) * 0.125f);
                    l0v += p4[nt4][0] + p4[nt4][1];
                    l1v += p4[nt4][2] + p4[nt4][3];
                } else {
                    {
                        int d0 = min(max(kg - r0, -32), 32) + 32;
                        int d1 = min(max(kg + 1 - r0, -32), 32) + 32;
                        float s0 = (c4[0] + QR[tr0*66 + d0]) * 0.125f;
                        float s1 = (c4[1] + QR[tr0*66 + d1]) * 0.125f;
                        p4[nt4][0] = (kg     <= r0) ? __expf(fminf(s0, 80.f)) : 0.f;
                        p4[nt4][1] = (kg + 1 <= r0) ? __expf(fminf(s1, 80.f)) : 0.f;
                        l0v += p4[nt4][0] + p4[nt4][1];
                    }
                    {
                        int d0 = min(max(kg - r1, -32), 32) + 32;
                        int d1 = min(max(kg + 1 - r1, -32), 32) + 32;
                        float s0 = (c4[2] + QR[(tr0+8)*66 + d0]) * 0.125f;
                        float s1 = (c4[3] + QR[(tr0+8)*66 + d1]) * 0.125f;
                        p4[nt4][2] = (kg     <= r1) ? __expf(fminf(s0, 80.f)) : 0.f;
                        p4[nt4][3] = (kg + 1 <= r1) ? __expf(fminf(s1, 80.f)) : 0.f;
                        l1v += p4[nt4][2] + p4[nt4][3];
                    }
                }
                *(float2*)&att[ab0 + kbase + t2] = make_float2(p4[nt4][0], p4[nt4][1]);
                *(float2*)&att[ab1 + kbase + t2] = make_float2(p4[nt4][2], p4[nt4][3]);
            }
            #pragma unroll
            for (int ksl = 0; ksl < 2; ksl++) {
                int kslice = kc + ss2*32 + ksl*16;
                if (kslice <= wmax) {
                    uint32_t ah[4], al[4];
                    ah[0] = pack_hi_lo(p4[2*ksl][0],   p4[2*ksl][1],   al[0]);
                    ah[1] = pack_hi_lo(p4[2*ksl][2],   p4[2*ksl][3],   al[1]);
                    ah[2] = pack_hi_lo(p4[2*ksl+1][0], p4[2*ksl+1][1], al[2]);
                    ah[3] = pack_hi_lo(p4[2*ksl+1][2], p4[2*ksl+1][3], al[3]);
                    int kloc = ss2*32 + ksl*16 + t2;
                    #pragma unroll
                    for (int dt = 0; dt < 8; dt++) {
                        int db = (dt*8 + g)*SVW + kloc;
                        uint32_t bh2[2], bl2[2];
                        bh2[0] = *(const uint32_t*)&sVh[db];
                        bh2[1] = *(const uint32_t*)&sVh[db + 8];
                        bl2[0] = *(const uint32_t*)&sVl[db];
                        bl2[1] = *(const uint32_t*)&sVl[db + 8];
                        mma_16816(o[dt], ah, bh2);
                        mma_16816(o[dt], ah, bl2);
                        mma_16816(o[dt], al, bh2);
                    }
                }
            }
        }
        __syncthreads();             // protect buffer before next-next stage
    }

    // ---- merge l across the quad (4 lanes share each row) ----
    #pragma unroll
    for (int off = 1; off <= 2; off <<= 1) {
        l0v += __shfl_xor_sync(0xffffffffu, l0v, off);
        l1v += __shfl_xor_sync(0xffffffffu, l1v, off);
    }
    const float inv0 = 1.f / l0v, inv1 = 1.f / l1v;
    if ((lane & 3) == 0) {
        sInv[tr0]     = inv0;
        sInv[tr0 + 8] = inv1;
    }

    // ---- write O scaled, directly as bf16 hi/lo (fused split for proj) ----
    {
        int b_ = bh >> 4, h_ = bh & 15;
        size_t ob0 = ((size_t)b_*TT + r0)*CC + h_*64;
        size_t ob1 = ((size_t)b_*TT + r1)*CC + h_*64;
        #pragma unroll
        for (int dt = 0; dt < 8; dt++) {
            uint32_t lo0, lo1;
            uint32_t hi0 = pack_hi_lo(o[dt][0]*inv0, o[dt][1]*inv0, lo0);
            uint32_t hi1 = pack_hi_lo(o[dt][2]*inv1, o[dt][3]*inv1, lo1);
            *(uint32_t*)&g_oa_hi[ob0 + dt*8 + t2] = hi0;
            *(uint32_t*)&g_oa_lo[ob0 + dt*8 + t2] = lo0;
            *(uint32_t*)&g_oa_hi[ob1 + dt*8 + t2] = hi1;
            *(uint32_t*)&g_oa_lo[ob1 + dt*8 + t2] = lo1;
        }
    }

    // ---- zero-fill att cols [kend, TT) ----
    {
        int zc4 = (TT - kend) >> 2;
        float4 z = make_float4(0.f, 0.f, 0.f, 0.f);
        if (zc4 > 0) {
            for (int i = tid; i < BLKM*zc4; i += NTH) {
                int row = i / zc4;
                int c4i = i - row*zc4;
                *(float4*)&att[(qbase + q0 + row)*TT + kend + c4i*4] = z;
            }
        }
    }

    // ---- in-CTA normalization sweep (rows just written, L2-hot) ----
    __syncthreads();
    for (int row = w; row < BLKM; row += 16) {
        float inv = sInv[row];
        int n = q0 + row + 1;
        int n4 = (n + 3) >> 2;
        float4* p = (float4*)(att + (qbase + q0 + row) * TT);
        for (int i = lane; i < n4; i += 32) {
            float4 v = p[i];
            v.x *= inv; v.y *= inv; v.z *= inv; v.w *= inv;
            p[i] = v;
        }
    }
}

// =====================================================================
extern "C" void kernel_launch(void* const* d_in, const int* in_sizes, int n_in,
                              void* d_out, int out_size)
{
    const float* x      = (const float*)d_in[0];
    const float* w_attn = (const float*)d_in[2];
    const float* b_attn = (const float*)d_in[3];
    const float* w_proj = (const float*)d_in[4];
    const float* b_proj = (const float*)d_in[5];
    const float* rel_k  = (const float*)d_in[6];
    float* out = (float*)d_out;

    const size_t YS = (size_t)BT*CC;
    const size_t AS = (size_t)BH*TT*TT;

    float* y_out = out;
    float* att_base = nullptr;
    int att_mode = 1;
    if ((size_t)out_size >= YS + AS) {
        y_out = out; att_base = out + YS; att_mode = 0;
    } else if ((size_t)out_size == AS) {
        att_base = out; att_mode = 0; y_out = nullptr;
    }

    cudaFuncSetAttribute(attn_kernel,
        cudaFuncAttributeMaxDynamicSharedMemorySize, ATTN_SMEM_BYTES);
    cudaFuncSetAttribute(mma_gemm_kernel<0>,
        cudaFuncAttributeMaxDynamicSharedMemorySize, GEMM_SMEM_BYTES);
    cudaFuncSetAttribute(mma_gemm_kernel<1>,
        cudaFuncAttributeMaxDynamicSharedMemorySize, GEMM_SMEM_BYTES);

    split_kernel<<<BT*CC/4/256, 256>>>(x);
    wsplit_kernel<0><<<dim3(3*CC/32, CC/32), dim3(32,8)>>>(w_attn, 3*CC);
    wsplit_kernel<1><<<dim3(CC/32,   CC/32), dim3(32,8)>>>(w_proj, CC);
    mma_gemm_kernel<0><<<dim3(24, 32), 256, GEMM_SMEM_BYTES>>>(b_attn, nullptr);
    qrel_kernel<<<BH*TT/32, 256>>>(rel_k);
    attn_kernel<<<dim3(TT/BLKM, BH), NTH, ATTN_SMEM_BYTES>>>(att_base, att_mode);
    mma_gemm_kernel<1><<<dim3(8, 32), 256, GEMM_SMEM_BYTES>>>(b_proj, y_out);
}